// round 6
// baseline (speedup 1.0000x reference)
#include <cuda_runtime.h>
#include <cstdint>

#define U64 unsigned long long

// ---------------- scratch (static device memory; no allocation) ----------------
__device__ float2 g_Wt2[128u*32u*1024u];  // Wt2[x][c][i*32+j] = W[x,i,c,j]   (33.5 MB)
__device__ float2 g_Hf [128u*256u*256u];  // Hf[x][b*32+i][t]                 (67 MB)
__device__ float2 g_D  [128u*255u*256u];  // D[x][t][b*32+c] = dx             (66.8 MB)
__device__ float2 g_Z0f[128u*256u];       // Z0f[x][b*32+i]
__device__ float2 g_Zs [256u*256u*128u];  // Zs[b*32+i][t][x]                 (67 MB)
__device__ float  g_Fz [256u*128u];
__device__ float  g_Gz [256u*8u*128u];

// ---------------- helpers ----------------
__device__ __forceinline__ U64 pk2(float lo, float hi){
    U64 r; asm("mov.b64 %0, {%1, %2};" : "=l"(r) : "f"(lo), "f"(hi)); return r;
}
__device__ __forceinline__ float2 upk2(U64 v){
    float lo, hi; asm("mov.b64 {%0, %1}, %2;" : "=f"(lo), "=f"(hi) : "l"(v));
    return make_float2(lo, hi);
}
#define FMA2(acc, a, b) asm("fma.rn.f32x2 %0, %1, %2, %0;" : "+l"(acc) : "l"(a), "l"(b))

__device__ __forceinline__ int rev7(int v){ return (int)(__brev((unsigned)v) >> 25); }

__device__ __forceinline__ void build_tw(float2* tw, int tid, float sign){
    if (tid < 64){
        float ang = sign * 6.28318530717958647692f * (float)tid * (1.0f/128.0f);
        float s, c; __sincosf(ang, &s, &c);
        tw[tid] = make_float2(c, s);
    }
}

__device__ __forceinline__ void fft_inplace(float2* buf, int nt, const float2* tw,
                                            int tid, int nth){
    #pragma unroll
    for (int s = 0; s < 7; s++){
        int half = 1 << s;
        int nbf = nt << 6;
        for (int idx = tid; idx < nbf; idx += nth){
            int q   = idx & 63;
            int row = idx >> 6;
            int p   = q & (half - 1);
            int g   = q >> s;
            int i0  = row * 128 + g * (half << 1) + p;
            float2 a = buf[i0], b = buf[i0 + half];
            float2 w = tw[p << (6 - s)];
            float2 t = make_float2(w.x*b.x - w.y*b.y, w.x*b.y + w.y*b.x);
            buf[i0]        = make_float2(a.x + t.x, a.y + t.y);
            buf[i0 + half] = make_float2(a.x - t.x, a.y - t.y);
        }
        __syncthreads();
    }
}

// ---------------- K0: W -> [x][c][ij] layout ----------------
// grid (128, 32) = (x, c), 1024 threads = i*32+j
__global__ void k0_wt2(const float* __restrict__ Wr, const float* __restrict__ Wi){
    int x = blockIdx.x, c = blockIdx.y;
    int tid = threadIdx.x;
    int i = tid >> 5, j = tid & 31;
    size_t src = (((size_t)(x*32 + i))*32 + c)*32 + j;
    g_Wt2[((size_t)(x*32 + c))*1024 + tid] = make_float2(Wr[src], Wi[src]);
}

// ---------------- K1: Fz0 = A z0, Gz0 = Gw z0 ----------------
__global__ void k1_proj(const float* __restrict__ z0, const float* __restrict__ A,
                        const float* __restrict__ Gw){
    int bi = blockIdx.x; int b = bi >> 5, i = bi & 31;
    int x = threadIdx.x;
    float zv[32];
    #pragma unroll
    for (int h = 0; h < 32; h++) zv[h] = z0[((size_t)(b*32 + h))*128 + x];
    float f = 0.f;
    #pragma unroll
    for (int h = 0; h < 32; h++) f += A[i*32 + h] * zv[h];
    g_Fz[bi*128 + x] = f;
    for (int fi = 0; fi < 8; fi++){
        float g = 0.f;
        #pragma unroll
        for (int h = 0; h < 32; h++) g += Gw[(i*8 + fi)*32 + h] * zv[h];
        g_Gz[(bi*8 + fi)*128 + x] = g;
    }
}

// ---------------- K2b: fftshift(fft_x(z0)) ----------------
__global__ void k2b_z0fft(const float* __restrict__ z0){
    __shared__ float2 buf[128];
    __shared__ float2 tw[64];
    int bi = blockIdx.x;
    int tid = threadIdx.x;
    build_tw(tw, tid, -1.f);
    buf[rev7(tid)] = make_float2(z0[(size_t)bi*128 + tid], 0.f);
    __syncthreads();
    fft_inplace(buf, 1, tw, tid, 128);
    int xs = (tid + 64) & 127;
    g_Z0f[xs*256 + bi] = buf[tid];
}

// ---------------- K2: Hu + FFT_x + shift -> g_Hf ----------------
__global__ void k2_hufft(const float* __restrict__ xi){
    __shared__ float2 buf[16*128];
    __shared__ float  Gl[8*128];
    __shared__ float  Fl[128];
    __shared__ float2 tw[64];
    int bi = blockIdx.x; int b = bi >> 5;
    int t0 = blockIdx.y * 16;
    int tid = threadIdx.x;
    build_tw(tw, tid, -1.f);
    if (tid < 128) Fl[tid] = g_Fz[bi*128 + tid];
    for (int idx = tid; idx < 1024; idx += 256) Gl[idx] = g_Gz[(size_t)bi*1024 + idx];
    __syncthreads();
    #pragma unroll
    for (int k = 0; k < 8; k++){
        int idx = tid + k*256;
        int tt = idx & 15, x = idx >> 4;
        float hu = Fl[x];
        #pragma unroll
        for (int f = 0; f < 8; f++)
            hu += Gl[f*128 + x] * xi[((size_t)(b*8 + f)*128 + x)*256 + t0 + tt];
        buf[tt*128 + rev7(x)] = make_float2(hu, 0.f);
    }
    __syncthreads();
    fft_inplace(buf, 16, tw, tid, 256);
    #pragma unroll
    for (int k = 0; k < 8; k++){
        int idx = tid + k*256;
        int tt = idx & 15, xk = idx >> 4;
        int xs = (xk + 64) & 127;
        g_Hf[(size_t)xs*65536 + (size_t)bi*256 + t0 + tt] = buf[tt*128 + xk];
    }
}

// ---------------- KD: dx precompute -> g_D[x][t][b*32+c] ----------------
// grid (128, 255) = (x, t); 256 threads = b*32 + c
__global__ void kD_dx(){
    int x = blockIdx.x, t = blockIdx.y;
    int tid = threadIdx.x;
    const float2* hp = g_Hf + (size_t)x*65536 + (size_t)tid*256 + t;
    float2 h0 = hp[0], h1 = hp[1];
    g_D[((size_t)x*255 + t)*256 + tid] = make_float2(h1.x - h0.x, h1.y - h0.y);
}

// ---------------- K3c: fused M-contraction + scan ----------------
// grid 128 (x), 1024 threads; warp = i, lane = j
// Per step: M[b,i,j] = sum_c W[x,i,c,j] dx[b,c] (Gauss, z-independent, bulk fma work)
//           dz[b,i]  = sum_j M[b,i,j] z[b,j]     (tiny serial tail)
__global__ __launch_bounds__(1024, 1) void k3c_scan(){
    __shared__ float  s_dx[2][32][24];  // [ring][c][plane*8+b]: r 0-7, i 8-15, s 16-23
    __shared__ float2 s_z [2][8][32];   // [ring][b][h]
    int x    = blockIdx.x;
    int tid  = threadIdx.x;
    int lane = tid & 31;   // j
    int wi   = tid >> 5;   // i
    const float2* Wp = g_Wt2 + (size_t)x*32768 + tid;   // + c*1024

    // prologue: z0 and dx[t=0]
    if (tid < 256){
        s_z[0][tid >> 5][tid & 31] = g_Z0f[x*256 + tid];
        float2 d = g_D[(size_t)x*65280 + tid];          // t = 0
        int b = tid >> 5, c = tid & 31;
        s_dx[0][c][b]      = d.x;
        s_dx[0][c][8 + b]  = d.y;
        s_dx[0][c][16 + b] = d.x + d.y;
    }
    __syncthreads();

    bool t4 = (lane & 16) != 0, t3 = (lane & 8) != 0;
    bool t2 = (lane & 4)  != 0, t1 = (lane & 2) != 0;

    for (int t = 0; t < 255; t++){
        int rg = t & 1;
        // store z_t; prefetch dx for t+1 into the other ring
        if (tid < 256){
            int bb = tid >> 5, hh = tid & 31;
            g_Zs[(size_t)tid*32768 + (size_t)t*128 + x] = s_z[rg][bb][hh];
            if (t < 254){
                float2 d = g_D[((size_t)x*255 + (t + 1))*256 + tid];
                int c = hh;
                s_dx[rg ^ 1][c][bb]      = d.x;
                s_dx[rg ^ 1][c][8 + bb]  = d.y;
                s_dx[rg ^ 1][c][16 + bb] = d.x + d.y;
            }
        }

        // M-contraction (z-independent): P=sum wr*dr, Q=sum wi*di, S=sum ws*ds
        U64 P[4] = {0,0,0,0}, Q[4] = {0,0,0,0}, S[4] = {0,0,0,0};
        #pragma unroll 4
        for (int c = 0; c < 32; c++){
            float2 w = Wp[(size_t)c*1024];
            float ws = w.x + w.y;
            U64 wrr = pk2(w.x, w.x);
            U64 wii = pk2(w.y, w.y);
            U64 wss = pk2(ws, ws);
            const ulonglong2* dp = (const ulonglong2*)&s_dx[rg][c][0];
            ulonglong2 dra = dp[0], drb = dp[1];
            ulonglong2 dia = dp[2], dib = dp[3];
            ulonglong2 dsa = dp[4], dsb = dp[5];
            FMA2(P[0], wrr, dra.x); FMA2(P[1], wrr, dra.y);
            FMA2(P[2], wrr, drb.x); FMA2(P[3], wrr, drb.y);
            FMA2(Q[0], wii, dia.x); FMA2(Q[1], wii, dia.y);
            FMA2(Q[2], wii, dib.x); FMA2(Q[3], wii, dib.y);
            FMA2(S[0], wss, dsa.x); FMA2(S[1], wss, dsa.y);
            FMA2(S[2], wss, dsb.x); FMA2(S[3], wss, dsb.y);
        }

        // resolve M and matvec against z_t: contrib[b] = M[b]*z[b,lane]
        float v[16];
        #pragma unroll
        for (int k = 0; k < 4; k++){
            float2 p = upk2(P[k]), q = upk2(Q[k]), s = upk2(S[k]);
            float mr0 = p.x - q.x, mi0 = s.x - p.x - q.x;
            float mr1 = p.y - q.y, mi1 = s.y - p.y - q.y;
            float2 za = s_z[rg][2*k][lane];
            float2 zb = s_z[rg][2*k + 1][lane];
            v[4*k + 0] = mr0*za.x - mi0*za.y;
            v[4*k + 1] = mr0*za.y + mi0*za.x;
            v[4*k + 2] = mr1*zb.x - mi1*zb.y;
            v[4*k + 3] = mr1*zb.y + mi1*zb.x;
        }

        // value-halving butterfly: 16 sums over 32 lanes (31 shfl)
        #pragma unroll
        for (int m = 0; m < 8; m++){
            float a0 = v[m]     + __shfl_xor_sync(0xffffffffu, v[m],     16);
            float a1 = v[m + 8] + __shfl_xor_sync(0xffffffffu, v[m + 8], 16);
            v[m] = t4 ? a1 : a0;
        }
        #pragma unroll
        for (int m = 0; m < 4; m++){
            float a0 = v[m]     + __shfl_xor_sync(0xffffffffu, v[m],     8);
            float a1 = v[m + 4] + __shfl_xor_sync(0xffffffffu, v[m + 4], 8);
            v[m] = t3 ? a1 : a0;
        }
        #pragma unroll
        for (int m = 0; m < 2; m++){
            float a0 = v[m]     + __shfl_xor_sync(0xffffffffu, v[m],     4);
            float a1 = v[m + 2] + __shfl_xor_sync(0xffffffffu, v[m + 2], 4);
            v[m] = t2 ? a1 : a0;
        }
        {
            float a0 = v[0] + __shfl_xor_sync(0xffffffffu, v[0], 2);
            float a1 = v[1] + __shfl_xor_sync(0xffffffffu, v[1], 2);
            v[0] = t1 ? a1 : a0;
        }
        v[0] += __shfl_xor_sync(0xffffffffu, v[0], 1);
        // even lane l: total for b = (l>>2)&7, comp = (l>>1)&1

        // update z[b][wi] into the other ring
        if (!(lane & 1)){
            int b    = (lane >> 2) & 7;
            int comp = (lane >> 1) & 1;
            float zc = ((const float*)&s_z[rg][b][wi])[comp];
            ((float*)&s_z[rg ^ 1][b][wi])[comp] = zc + v[0];
        }
        __syncthreads();
    }
    // final state t = 255 sits in ring (254^1)&... = s_z[1]
    if (tid < 256){
        int bb = tid >> 5, hh = tid & 31;
        g_Zs[(size_t)tid*32768 + (size_t)255*128 + x] = s_z[1][bb][hh];
    }
}

// ---------------- K4: ifftshift + IFFT_x + real part -> out ----------------
__global__ void k4_ifft(float* __restrict__ out){
    __shared__ float2 buf[16*128];
    __shared__ float2 tw[64];
    int bi = blockIdx.x;
    int t0 = blockIdx.y * 16;
    int tid = threadIdx.x;
    build_tw(tw, tid, +1.f);
    #pragma unroll
    for (int k = 0; k < 8; k++){
        int idx = tid + k*256;
        int m = idx & 127, tt = idx >> 7;
        float2 v = g_Zs[(size_t)bi*32768 + (size_t)(t0 + tt)*128 + ((m + 64) & 127)];
        buf[tt*128 + rev7(m)] = v;
    }
    __syncthreads();
    fft_inplace(buf, 16, tw, tid, 256);
    #pragma unroll
    for (int k = 0; k < 8; k++){
        int idx = tid + k*256;
        int tt = idx & 15, n = idx >> 4;
        out[((size_t)bi*128 + n)*256 + t0 + tt] = buf[tt*128 + n].x * (1.0f/128.0f);
    }
}

// ---------------- launch ----------------
extern "C" void kernel_launch(void* const* d_in, const int* in_sizes, int n_in,
                              void* d_out, int out_size){
    const float* z0 = (const float*)d_in[0];
    const float* xi = (const float*)d_in[1];
    const float* A  = (const float*)d_in[2];
    const float* Gw = (const float*)d_in[3];
    const float* Wr = (const float*)d_in[4];
    const float* Wi = (const float*)d_in[5];
    float* out = (float*)d_out;

    k0_wt2<<<dim3(128, 32), 1024>>>(Wr, Wi);          // launch 1
    k1_proj<<<256, 128>>>(z0, A, Gw);                 // launch 2
    k2b_z0fft<<<256, 128>>>(z0);                      // launch 3
    k2_hufft<<<dim3(256, 16), 256>>>(xi);             // launch 4
    kD_dx<<<dim3(128, 255), 256>>>();                 // launch 5
    k3c_scan<<<128, 1024>>>();                        // launch 6 (ncu -s 5 target)
    k4_ifft<<<dim3(256, 16), 256>>>(out);             // launch 7
    (void)in_sizes; (void)n_in; (void)out_size;
}